// round 2
// baseline (speedup 1.0000x reference)
#include <cuda_runtime.h>
#include <math.h>

// Problem constants (fixed shapes per reference):
//   user_emb:      (4096, 768) f32
//   pos_item_emb:  (4096, 768) f32
//   neg_indices:   (4096, 60)  i32
//   output:        scalar f32 (mean CE loss, label 0)
#define B_ROWS 4096
#define DIM    768
#define KNEG   60
#define NLOGIT (KNEG + 1)
#define D4     (DIM / 4)        // 192 float4 per row
#define CHUNKS (D4 / 32)        // 6 float4 per lane

// Scratch for per-row losses (device global: no allocation allowed).
__device__ float g_row_loss[B_ROWS];

__global__ __launch_bounds__(256, 8)
void row_loss_kernel(const float* __restrict__ U,
                     const float* __restrict__ P,
                     const int*   __restrict__ IDX) {
    const int b    = blockIdx.x;
    const int wid  = threadIdx.x >> 5;
    const int lane = threadIdx.x & 31;

    __shared__ float s_logits[NLOGIT];
    __shared__ int   s_idx[KNEG];

    if (threadIdx.x < KNEG)
        s_idx[threadIdx.x] = IDX[b * KNEG + threadIdx.x];

    // Cache this row's user embedding in registers: lane owns float4
    // chunks {lane, lane+32, ..., lane+160} -> coalesced 128B sectors.
    const float4* u4 = reinterpret_cast<const float4*>(U + (size_t)b * DIM);
    float4 u[CHUNKS];
#pragma unroll
    for (int i = 0; i < CHUNKS; i++)
        u[i] = u4[lane + 32 * i];

    __syncthreads();

    // 61 logits split across 8 warps: k=0 is the positive, k>=1 negatives.
    for (int k = wid; k < NLOGIT; k += 8) {
        const int row = (k == 0) ? b : s_idx[k - 1];
        const float4* p4 = reinterpret_cast<const float4*>(P + (size_t)row * DIM);
        float acc = 0.0f;
#pragma unroll
        for (int i = 0; i < CHUNKS; i++) {
            float4 p = p4[lane + 32 * i];
            acc += u[i].x * p.x;
            acc += u[i].y * p.y;
            acc += u[i].z * p.z;
            acc += u[i].w * p.w;
        }
#pragma unroll
        for (int off = 16; off > 0; off >>= 1)
            acc += __shfl_down_sync(0xFFFFFFFFu, acc, off);
        if (lane == 0)
            s_logits[k] = acc;
    }
    __syncthreads();

    // Warp 0: numerically-stable log-softmax over 61 logits.
    if (wid == 0) {
        float v0 = (lane < NLOGIT) ? s_logits[lane] : -INFINITY;
        float v1 = (lane + 32 < NLOGIT) ? s_logits[lane + 32] : -INFINITY;
        float m = fmaxf(v0, v1);
#pragma unroll
        for (int off = 16; off > 0; off >>= 1)
            m = fmaxf(m, __shfl_xor_sync(0xFFFFFFFFu, m, off));
        float e = 0.0f;
        if (lane < NLOGIT)      e += expf(v0 - m);
        if (lane + 32 < NLOGIT) e += expf(v1 - m);
#pragma unroll
        for (int off = 16; off > 0; off >>= 1)
            e += __shfl_xor_sync(0xFFFFFFFFu, e, off);
        if (lane == 0)
            g_row_loss[b] = (m + logf(e)) - s_logits[0];
    }
}

__global__ __launch_bounds__(256, 1)
void mean_reduce_kernel(float* __restrict__ out) {
    __shared__ float sh[256];
    float s = 0.0f;
    for (int i = threadIdx.x; i < B_ROWS; i += 256)
        s += g_row_loss[i];
    sh[threadIdx.x] = s;
    __syncthreads();
#pragma unroll
    for (int st = 128; st > 0; st >>= 1) {
        if (threadIdx.x < st)
            sh[threadIdx.x] += sh[threadIdx.x + st];
        __syncthreads();
    }
    if (threadIdx.x == 0)
        out[0] = sh[0] * (1.0f / (float)B_ROWS);
}

extern "C" void kernel_launch(void* const* d_in, const int* in_sizes, int n_in,
                              void* d_out, int out_size) {
    const float* U   = (const float*)d_in[0];   // user_emb (B, D)
    const float* P   = (const float*)d_in[1];   // pos_item_emb (B, D)
    const int*   IDX = (const int*)  d_in[2];   // neg_indices (B, K)
    float* out = (float*)d_out;

    row_loss_kernel<<<B_ROWS, 256>>>(U, P, IDX);
    mean_reduce_kernel<<<1, 256>>>(out);
}

// round 6
// speedup vs baseline: 1.3204x; 1.3204x over previous
#include <cuda_runtime.h>
#include <cuda_bf16.h>
#include <math.h>

// Shapes (fixed): user_emb (4096,768) f32, pos_item_emb (4096,768) f32,
// neg_indices (4096,60) i32, output scalar f32 (mean CE, label 0).
#define B_ROWS  4096
#define DIM     768
#define KNEG    60
#define NLOGIT  (KNEG + 1)
#define ROW_U4  (DIM / 8)     // 96 uint4 per bf16 row (1536 B)
#define PCHUNKS 3             // uint4 per lane per row (3 * 32 = 96)

// bf16 copy of the item table (L2-resident: 6.3 MB) + fixed-point loss accum.
__device__ __align__(16) unsigned int g_Pb[B_ROWS * DIM / 2];
__device__ unsigned long long g_acc;

// Fixed-point scale for the deterministic integer accumulation.
#define FP_SCALE 1073741824.0f   /* 2^30 */

__device__ __forceinline__ float blo(unsigned int u) {  // bf16 pair, low elem
    return __uint_as_float(u << 16);
}
__device__ __forceinline__ float bhi(unsigned int u) {  // bf16 pair, high elem
    return __uint_as_float(u & 0xFFFF0000u);
}

// ---------------------------------------------------------------------------
// Kernel 1: f32 item table -> bf16 device table; also zero the accumulator.
// One thread packs 8 floats -> one uint4 of 4 bf16 pairs.
// ---------------------------------------------------------------------------
__global__ __launch_bounds__(256)
void convert_kernel(const float* __restrict__ P) {
    const int t = blockIdx.x * blockDim.x + threadIdx.x;
    if (t == 0) g_acc = 0ULL;

    const float4* p4 = reinterpret_cast<const float4*>(P);
    float4 a = p4[2 * t];
    float4 c = p4[2 * t + 1];

    __nv_bfloat162 b0 = __float22bfloat162_rn(make_float2(a.x, a.y));
    __nv_bfloat162 b1 = __float22bfloat162_rn(make_float2(a.z, a.w));
    __nv_bfloat162 b2 = __float22bfloat162_rn(make_float2(c.x, c.y));
    __nv_bfloat162 b3 = __float22bfloat162_rn(make_float2(c.z, c.w));

    uint4 o;
    o.x = *reinterpret_cast<unsigned int*>(&b0);
    o.y = *reinterpret_cast<unsigned int*>(&b1);
    o.z = *reinterpret_cast<unsigned int*>(&b2);
    o.w = *reinterpret_cast<unsigned int*>(&b3);
    reinterpret_cast<uint4*>(g_Pb)[t] = o;
}

// ---------------------------------------------------------------------------
// Kernel 2: per-row logits (1 pos + 60 gathered negs), log-softmax CE,
// fixed-point atomic accumulation (deterministic: integer atomics).
// ---------------------------------------------------------------------------
__global__ __launch_bounds__(256, 8)
void row_loss_kernel(const float* __restrict__ U,
                     const int*   __restrict__ IDX) {
    const int b    = blockIdx.x;
    const int wid  = threadIdx.x >> 5;
    const int lane = threadIdx.x & 31;

    __shared__ float s_logits[NLOGIT];
    __shared__ int   s_idx[KNEG];

    if (threadIdx.x < KNEG)
        s_idx[threadIdx.x] = IDX[b * KNEG + threadIdx.x];

    // Cache this row's user embedding (f32) in registers, element-mapped to
    // the bf16 uint4 layout: chunk i covers elems [8*(lane+32i), +7].
    float u[PCHUNKS * 8];
    {
        const float4* u4 = reinterpret_cast<const float4*>(U + (size_t)b * DIM);
#pragma unroll
        for (int i = 0; i < PCHUNKS; i++) {
            float4 a = u4[2 * (lane + 32 * i)];
            float4 c = u4[2 * (lane + 32 * i) + 1];
            u[i * 8 + 0] = a.x; u[i * 8 + 1] = a.y;
            u[i * 8 + 2] = a.z; u[i * 8 + 3] = a.w;
            u[i * 8 + 4] = c.x; u[i * 8 + 5] = c.y;
            u[i * 8 + 6] = c.z; u[i * 8 + 7] = c.w;
        }
    }
    __syncthreads();

    const uint4* Pb = reinterpret_cast<const uint4*>(g_Pb);

    // 61 logits across 8 warps: k=0 positive, k>=1 negatives.
    for (int k = wid; k < NLOGIT; k += 8) {
        const int row = (k == 0) ? b : s_idx[k - 1];
        const uint4* p = Pb + (size_t)row * ROW_U4;
        float acc = 0.0f;
#pragma unroll
        for (int i = 0; i < PCHUNKS; i++) {
            uint4 v = p[lane + 32 * i];
            acc = fmaf(u[i * 8 + 0], blo(v.x), acc);
            acc = fmaf(u[i * 8 + 1], bhi(v.x), acc);
            acc = fmaf(u[i * 8 + 2], blo(v.y), acc);
            acc = fmaf(u[i * 8 + 3], bhi(v.y), acc);
            acc = fmaf(u[i * 8 + 4], blo(v.z), acc);
            acc = fmaf(u[i * 8 + 5], bhi(v.z), acc);
            acc = fmaf(u[i * 8 + 6], blo(v.w), acc);
            acc = fmaf(u[i * 8 + 7], bhi(v.w), acc);
        }
#pragma unroll
        for (int off = 16; off > 0; off >>= 1)
            acc += __shfl_down_sync(0xFFFFFFFFu, acc, off);
        if (lane == 0)
            s_logits[k] = acc;
    }
    __syncthreads();

    // Warp 0: stable log-softmax; loss = logsumexp - logits[0] (>= 0).
    if (wid == 0) {
        float v0 = (lane < NLOGIT) ? s_logits[lane] : -INFINITY;
        float v1 = (lane + 32 < NLOGIT) ? s_logits[lane + 32] : -INFINITY;
        float m = fmaxf(v0, v1);
#pragma unroll
        for (int off = 16; off > 0; off >>= 1)
            m = fmaxf(m, __shfl_xor_sync(0xFFFFFFFFu, m, off));
        float e = 0.0f;
        if (lane < NLOGIT)      e += expf(v0 - m);
        if (lane + 32 < NLOGIT) e += expf(v1 - m);
#pragma unroll
        for (int off = 16; off > 0; off >>= 1)
            e += __shfl_xor_sync(0xFFFFFFFFu, e, off);
        if (lane == 0) {
            float loss = (m + logf(e)) - s_logits[0];
            unsigned long long q =
                (unsigned long long)__float2ll_rn(loss * FP_SCALE);
            atomicAdd(&g_acc, q);
        }
    }
}

// ---------------------------------------------------------------------------
// Kernel 3: scale the fixed-point sum into the scalar mean.
// ---------------------------------------------------------------------------
__global__ void finalize_kernel(float* __restrict__ out) {
    out[0] = (float)((double)g_acc *
                     (1.0 / ((double)FP_SCALE * (double)B_ROWS)));
}

extern "C" void kernel_launch(void* const* d_in, const int* in_sizes, int n_in,
                              void* d_out, int out_size) {
    const float* U   = (const float*)d_in[0];   // user_emb (B, D)
    const float* P   = (const float*)d_in[1];   // pos_item_emb (B, D)
    const int*   IDX = (const int*)  d_in[2];   // neg_indices (B, K)
    float* out = (float*)d_out;

    convert_kernel<<<(B_ROWS * DIM / 8) / 256, 256>>>(P);
    row_loss_kernel<<<B_ROWS, 256>>>(U, IDX);
    finalize_kernel<<<1, 1>>>(out);
}